// round 1
// baseline (speedup 1.0000x reference)
#include <cuda_runtime.h>

#define BB 512
#define TT 200
#define MM 50
#define DKX 64
#define DVX 64
#define HHX 128
#define NSK 1000
#define NITEMS (BB*TT)

// ---- scratch (device globals; no runtime allocation allowed) ----
__device__ float g_w[NITEMS*MM];      // softmax attention weights  (B,T,M)
__device__ float g_e[NITEMS*DVX];     // erase gates (B,T,DV)
__device__ float g_a[NITEMS*DVX];     // add vectors (B,T,DV)
__device__ float g_read[NITEMS*DVX];  // scan reads  (B,T,DV)

// ============================================================================
// Kernel 1: per-item parallel precompute of w (softmax), e (sigmoid), a (tanh)
// One warp handles 4 items; K^T / erase_W / add_W cached in shared.
// ============================================================================
__global__ __launch_bounds__(256) void k1_precompute(
    const int*   __restrict__ skill_seq,
    const int*   __restrict__ correct_seq,
    const float* __restrict__ skill_embed,
    const float* __restrict__ key_memory,
    const float* __restrict__ interaction_embed,
    const float* __restrict__ erase_W,
    const float* __restrict__ erase_b,
    const float* __restrict__ add_W,
    const float* __restrict__ add_b)
{
    extern __shared__ float smem[];
    float* sKt = smem;                    // [64][52] transposed, padded
    float* seW = sKt + DKX*52;            // [64*64]
    float* saW = seW + DKX*DVX;           // [64*64]
    float* sq  = saW + DKX*DVX;           // [8 warps][4*64]
    float* sv  = sq  + 8*4*DKX;           // [8 warps][4*64]

    int tid = threadIdx.x;
    for (int idx = tid; idx < MM*DKX; idx += 256) {
        int m = idx / DKX, i = idx % DKX;
        sKt[i*52 + m] = key_memory[m*DKX + i];
    }
    for (int idx = tid; idx < DKX*DVX; idx += 256) {
        seW[idx] = erase_W[idx];
        saW[idx] = add_W[idx];
    }
    __syncthreads();

    int w    = tid >> 5;
    int lane = tid & 31;
    float eb0 = erase_b[lane], eb1 = erase_b[lane+32];
    float ab0 = add_b[lane],   ab1 = add_b[lane+32];
    float* mq = sq + w*4*DKX;
    float* mv = sv + w*4*DVX;

    const int nwarps  = gridDim.x * 8;
    const int ngroups = NITEMS / 4;
    const bool v1 = (lane + 32) < MM;   // lane < 18 handles m = lane+32

    for (int g = blockIdx.x*8 + w; g < ngroups; g += nwarps) {
        int base = g * 4;
        #pragma unroll
        for (int k = 0; k < 4; k++) {
            int item = base + k;
            int s = skill_seq[item];
            int c = correct_seq[item];
            mq[k*DKX + lane]    = skill_embed[s*DKX + lane];
            mq[k*DKX + lane+32] = skill_embed[s*DKX + lane+32];
            int vi = s + c*NSK;
            mv[k*DVX + lane]    = interaction_embed[vi*DVX + lane];
            mv[k*DVX + lane+32] = interaction_embed[vi*DVX + lane+32];
        }
        __syncwarp();

        // ---- attention logits: m = lane and lane+32 (if valid), 4 items ----
        float d0[4] = {0,0,0,0}, d1[4] = {0,0,0,0};
        #pragma unroll 8
        for (int i = 0; i < DKX; i++) {
            float k0 = sKt[i*52 + lane];
            float k1 = sKt[i*52 + lane + 32];
            #pragma unroll
            for (int k = 0; k < 4; k++) {
                float qi = mq[k*DKX + i];
                d0[k] = fmaf(qi, k0, d0[k]);
                d1[k] = fmaf(qi, k1, d1[k]);
            }
        }
        #pragma unroll
        for (int k = 0; k < 4; k++) {
            float mx = fmaxf(d0[k], v1 ? d1[k] : -1e30f);
            #pragma unroll
            for (int off = 16; off > 0; off >>= 1)
                mx = fmaxf(mx, __shfl_xor_sync(0xffffffffu, mx, off));
            float x0 = __expf(d0[k] - mx);
            float x1 = v1 ? __expf(d1[k] - mx) : 0.f;
            float s  = x0 + x1;
            #pragma unroll
            for (int off = 16; off > 0; off >>= 1)
                s += __shfl_xor_sync(0xffffffffu, s, off);
            float inv = 1.f / s;
            int item = base + k;
            g_w[item*MM + lane] = x0 * inv;
            if (v1) g_w[item*MM + lane + 32] = x1 * inv;
        }

        // ---- e = sigmoid(v @ eW + eb), a = tanh(v @ aW + ab) ----
        float E0[4], E1[4], A0[4], A1[4];
        #pragma unroll
        for (int k = 0; k < 4; k++) { E0[k]=eb0; E1[k]=eb1; A0[k]=ab0; A1[k]=ab1; }
        #pragma unroll 4
        for (int i = 0; i < DVX; i++) {
            float w0 = seW[i*DVX + lane];
            float w1 = seW[i*DVX + lane+32];
            float u0 = saW[i*DVX + lane];
            float u1 = saW[i*DVX + lane+32];
            #pragma unroll
            for (int k = 0; k < 4; k++) {
                float vi = mv[k*DVX + i];
                E0[k] = fmaf(vi, w0, E0[k]);
                E1[k] = fmaf(vi, w1, E1[k]);
                A0[k] = fmaf(vi, u0, A0[k]);
                A1[k] = fmaf(vi, u1, A1[k]);
            }
        }
        #pragma unroll
        for (int k = 0; k < 4; k++) {
            int item = base + k;
            g_e[item*DVX + lane]    = 1.f/(1.f + __expf(-E0[k]));
            g_e[item*DVX + lane+32] = 1.f/(1.f + __expf(-E1[k]));
            g_a[item*DVX + lane]    = tanhf(A0[k]);
            g_a[item*DVX + lane+32] = tanhf(A1[k]);
        }
        __syncwarp();
    }
}

// ============================================================================
// Kernel 2: sequential memory scan. One block per batch element.
// 128 threads: thread = (v = tid>>1, half = tid&1), each holds 25 mem rows
// in registers. w_t double-buffered in smem; next step's w/e/a prefetched.
// read_t uses pre-update mem (matches jax.lax.scan semantics).
// ============================================================================
__global__ __launch_bounds__(128) void k2_scan(const float* __restrict__ value_init)
{
    __shared__ float sw[2][MM];
    int b    = blockIdx.x;
    int tid  = threadIdx.x;
    int v    = tid >> 1;
    int half = tid & 1;
    int moff = half * 25;

    float mem[25];
    #pragma unroll
    for (int m = 0; m < 25; m++) mem[m] = value_init[(moff + m)*DVX + v];

    const int base = b * TT;
    // prefetch t = 0
    float wreg = (tid < MM) ? g_w[base*MM + tid] : 0.f;
    float ev = g_e[base*DVX + v];
    float av = g_a[base*DVX + v];

    for (int t = 0; t < TT; t++) {
        if (tid < MM) sw[t & 1][tid] = wreg;
        float e = ev, a = av;
        __syncthreads();
        if (t + 1 < TT) {
            int it = base + t + 1;
            if (tid < MM) wreg = g_w[it*MM + tid];
            ev = g_e[it*DVX + v];
            av = g_a[it*DVX + v];
        }
        const float* swc = sw[t & 1];
        float r = 0.f;
        #pragma unroll
        for (int m = 0; m < 25; m++) {
            float wm = swc[moff + m];
            r = fmaf(wm, mem[m], r);                 // read with OLD mem
            float t1 = fmaf(-mem[m], e, a);          // a - mem*e
            mem[m]   = fmaf(wm, t1, mem[m]);         // mem + w*(a - mem*e)
        }
        r += __shfl_xor_sync(0xffffffffu, r, 1);     // combine the two halves
        if (half == 0) g_read[(base + t)*DVX + v] = r;
    }
}

// ============================================================================
// Kernel 3: output MLP. h = relu([q, read] @ W1 + b1); logit = h @ w2 + b2.
// W1 (64KB) in shared; one warp processes 8 items (lane owns 4 h-columns).
// Also writes the second output (correct * mask).
// ============================================================================
__global__ __launch_bounds__(256) void k3_mlp(
    const int*   __restrict__ skill_seq,
    const int*   __restrict__ correct_seq,
    const float* __restrict__ mask,
    const float* __restrict__ skill_embed,
    const float* __restrict__ fc1_W,
    const float* __restrict__ fc1_b,
    const float* __restrict__ fc2_W,
    const float* __restrict__ fc2_b,
    float*       __restrict__ out)
{
    extern __shared__ float smem[];
    float* sW1 = smem;                    // [128*128]
    float* sw2 = sW1 + HHX*HHX;           // [128]
    float* sb1 = sw2 + HHX;               // [128]
    float* sx  = sb1 + HHX;               // [8 warps][128*9] pad-9 (no STS conflicts)

    int tid = threadIdx.x;
    for (int idx = tid; idx < HHX*HHX; idx += 256) sW1[idx] = fc1_W[idx];
    if (tid < HHX) { sw2[tid] = fc2_W[tid]; sb1[tid] = fc1_b[tid]; }
    __syncthreads();
    float b2 = fc2_b[0];

    int w    = tid >> 5;
    int lane = tid & 31;
    float* myx = sx + w * (HHX * 9);

    const int nwarps  = gridDim.x * 8;
    const int ngroups = NITEMS / 8;

    for (int g = blockIdx.x*8 + w; g < ngroups; g += nwarps) {
        int base = g * 8;
        // stage x = [q(64), read(64)] transposed: myx[i*9 + k]
        #pragma unroll
        for (int k = 0; k < 8; k++) {
            int item = base + k;
            int s = skill_seq[item];
            myx[(lane)    *9 + k] = skill_embed[s*DKX + lane];
            myx[(lane+32) *9 + k] = skill_embed[s*DKX + lane+32];
            myx[(lane+64) *9 + k] = g_read[item*DVX + lane];
            myx[(lane+96) *9 + k] = g_read[item*DVX + lane+32];
        }
        __syncwarp();

        float acc[4][8];
        #pragma unroll
        for (int c = 0; c < 4; c++) {
            float bb = sb1[lane*4 + c];
            #pragma unroll
            for (int k = 0; k < 8; k++) acc[c][k] = bb;
        }
        #pragma unroll 4
        for (int j = 0; j < HHX; j++) {
            float4 wv = *(const float4*)&sW1[j*HHX + lane*4];
            float xk[8];
            #pragma unroll
            for (int k = 0; k < 8; k++) xk[k] = myx[j*9 + k];
            #pragma unroll
            for (int k = 0; k < 8; k++) {
                acc[0][k] = fmaf(wv.x, xk[k], acc[0][k]);
                acc[1][k] = fmaf(wv.y, xk[k], acc[1][k]);
                acc[2][k] = fmaf(wv.z, xk[k], acc[2][k]);
                acc[3][k] = fmaf(wv.w, xk[k], acc[3][k]);
            }
        }
        // relu + dot with w2, per-item warp reduction
        float part[8];
        #pragma unroll
        for (int k = 0; k < 8; k++) {
            float p = 0.f;
            #pragma unroll
            for (int c = 0; c < 4; c++) {
                float h = fmaxf(acc[c][k], 0.f);
                p = fmaf(h, sw2[lane*4 + c], p);
            }
            part[k] = p;
        }
        #pragma unroll
        for (int off = 16; off > 0; off >>= 1) {
            #pragma unroll
            for (int k = 0; k < 8; k++)
                part[k] += __shfl_xor_sync(0xffffffffu, part[k], off);
        }
        if (lane < 8) {
            int item = base + lane;
            float logit = part[lane] + b2;
            float p = 1.f / (1.f + __expf(-logit));
            float mk = mask[item];
            out[item]          = p * mk;
            out[NITEMS + item] = (float)correct_seq[item] * mk;
        }
        __syncwarp();
    }
}

// ============================================================================
extern "C" void kernel_launch(void* const* d_in, const int* in_sizes, int n_in,
                              void* d_out, int out_size) {
    const int*   skill_seq         = (const int*)  d_in[0];
    const int*   correct_seq       = (const int*)  d_in[1];
    const float* mask              = (const float*)d_in[2];
    const float* skill_embed       = (const float*)d_in[3];
    const float* key_memory        = (const float*)d_in[4];
    const float* value_init        = (const float*)d_in[5];
    const float* interaction_embed = (const float*)d_in[6];
    const float* erase_W           = (const float*)d_in[7];
    const float* erase_b           = (const float*)d_in[8];
    const float* add_W             = (const float*)d_in[9];
    const float* add_b             = (const float*)d_in[10];
    const float* fc1_W             = (const float*)d_in[11];
    const float* fc1_b             = (const float*)d_in[12];
    const float* fc2_W             = (const float*)d_in[13];
    const float* fc2_b             = (const float*)d_in[14];
    float* out = (float*)d_out;

    // dynamic smem sizes
    const int k1_smem = (DKX*52 + 2*DKX*DVX + 2*8*4*DKX) * sizeof(float);  // ~62.5 KB
    const int k3_smem = (HHX*HHX + 2*HHX + 8*HHX*9)      * sizeof(float);  // ~101 KB
    cudaFuncSetAttribute(k1_precompute, cudaFuncAttributeMaxDynamicSharedMemorySize, k1_smem);
    cudaFuncSetAttribute(k3_mlp,        cudaFuncAttributeMaxDynamicSharedMemorySize, k3_smem);

    k1_precompute<<<296, 256, k1_smem>>>(skill_seq, correct_seq, skill_embed,
                                         key_memory, interaction_embed,
                                         erase_W, erase_b, add_W, add_b);
    k2_scan<<<BB, 128>>>(value_init);
    k3_mlp<<<296, 256, k3_smem>>>(skill_seq, correct_seq, mask, skill_embed,
                                  fc1_W, fc1_b, fc2_W, fc2_b, out);
}